// round 2
// baseline (speedup 1.0000x reference)
#include <cuda_runtime.h>
#include <math.h>

#define NA   4096
#define CUT2 25.0f

// Scratch (no device allocation allowed): inverse box + box copy, per-row
// pair counts, and per-row exclusive offsets.
__device__ float g_mat[18];   // [0..8] inv(box) row-major, [9..17] box row-major
__device__ int   g_cnt[NA];
__device__ int   g_off[NA];

// ---------------------------------------------------------------------------
// 3x3 inverse via cofactors. Diagonal box => off-diagonals are exact zeros,
// diagonal entries are correctly-rounded quotients (matches linalg.inv here).
// ---------------------------------------------------------------------------
__global__ void k_prep(const float* __restrict__ box) {
    float b[9];
#pragma unroll
    for (int i = 0; i < 9; i++) b[i] = box[i];
    float c00 =  (b[4]*b[8] - b[5]*b[7]);
    float c01 = -(b[3]*b[8] - b[5]*b[6]);
    float c02 =  (b[3]*b[7] - b[4]*b[6]);
    float det = b[0]*c00 + b[1]*c01 + b[2]*c02;

    g_mat[0] = __fdiv_rn(c00, det);
    g_mat[3] = __fdiv_rn(c01, det);
    g_mat[6] = __fdiv_rn(c02, det);
    g_mat[1] = __fdiv_rn(-(b[1]*b[8] - b[2]*b[7]), det);
    g_mat[4] = __fdiv_rn( (b[0]*b[8] - b[2]*b[6]), det);
    g_mat[7] = __fdiv_rn(-(b[0]*b[7] - b[1]*b[6]), det);
    g_mat[2] = __fdiv_rn( (b[1]*b[5] - b[2]*b[4]), det);
    g_mat[5] = __fdiv_rn(-(b[0]*b[5] - b[2]*b[3]), det);
    g_mat[8] = __fdiv_rn( (b[0]*b[4] - b[1]*b[3]), det);
#pragma unroll
    for (int i = 0; i < 9; i++) g_mat[9 + i] = b[i];
}

// Minimum-image wrap + squared distance. Explicit _rn intrinsics forbid fma
// contraction so boundary decisions (d2 < 25) match the reference's op order.
// frac_k = sum_m delta_m * inv[m][k];  shift_m = sum_k round(frac_k) * box[k][m]
__device__ __forceinline__ float pair_d2(float dx, float dy, float dz,
                                         const float* m,
                                         float& ox, float& oy, float& oz) {
    float fx = __fadd_rn(__fadd_rn(__fmul_rn(dx, m[0]), __fmul_rn(dy, m[3])), __fmul_rn(dz, m[6]));
    float fy = __fadd_rn(__fadd_rn(__fmul_rn(dx, m[1]), __fmul_rn(dy, m[4])), __fmul_rn(dz, m[7]));
    float fz = __fadd_rn(__fadd_rn(__fmul_rn(dx, m[2]), __fmul_rn(dy, m[5])), __fmul_rn(dz, m[8]));
    float rx = rintf(fx), ry = rintf(fy), rz = rintf(fz);   // half-to-even == jnp.round
    float sx = __fadd_rn(__fadd_rn(__fmul_rn(rx, m[9]),  __fmul_rn(ry, m[12])), __fmul_rn(rz, m[15]));
    float sy = __fadd_rn(__fadd_rn(__fmul_rn(rx, m[10]), __fmul_rn(ry, m[13])), __fmul_rn(rz, m[16]));
    float sz = __fadd_rn(__fadd_rn(__fmul_rn(rx, m[11]), __fmul_rn(ry, m[14])), __fmul_rn(rz, m[17]));
    ox = __fsub_rn(dx, sx);
    oy = __fsub_rn(dy, sy);
    oz = __fsub_rn(dz, sz);
    return __fadd_rn(__fadd_rn(__fmul_rn(ox, ox), __fmul_rn(oy, oy)), __fmul_rn(oz, oz));
}

// ---------------------------------------------------------------------------
// One warp owns two rows {g, NA-1-g} (balances the upper triangle).
// COUNT pass: per-row hit count. FILL pass: ballot-rank compaction writes
// hits in exact (i, then j) row-major order at g_off[i].
// ---------------------------------------------------------------------------
template <bool FILL>
__global__ void __launch_bounds__(512)
k_pairs(const float* __restrict__ pos, float* __restrict__ out, int P) {
    __shared__ float sxs[NA], sys[NA], szs[NA];   // 48 KB (static limit)
    for (int t = threadIdx.x; t < NA; t += blockDim.x) {
        sxs[t] = pos[3 * t + 0];
        sys[t] = pos[3 * t + 1];
        szs[t] = pos[3 * t + 2];
    }
    __syncthreads();

    float m[18];
#pragma unroll
    for (int k = 0; k < 18; k++) m[k] = g_mat[k];

    const int gw   = (blockIdx.x * blockDim.x + threadIdx.x) >> 5;  // [0, 2048)
    const int lane = threadIdx.x & 31;
    const unsigned lt_mask = (1u << lane) - 1u;

#pragma unroll
    for (int half = 0; half < 2; half++) {
        const int i = half ? (NA - 1 - gw) : gw;
        const float xi = sxs[i], yi = sys[i], zi = szs[i];

        int cnt  = 0;
        int base = FILL ? g_off[i] : 0;

        for (int jb = i + 1; jb < NA; jb += 32) {   // uniform trip count across warp
            const int  j   = jb + lane;
            const bool act = (j < NA);
            const int  jj  = act ? j : 0;
            float ox, oy, oz;
            const float d2 = pair_d2(xi - sxs[jj], yi - sys[jj], zi - szs[jj],
                                     m, ox, oy, oz);
            const bool hit = act && (d2 < CUT2);
            const unsigned bal = __ballot_sync(0xffffffffu, hit);

            if (FILL) {
                if (hit) {
                    const int idx = base + __popc(bal & lt_mask);
                    out[idx]              = (float)i;                 // pair_i
                    out[(size_t)P + idx]  = (float)j;                 // pair_j
                    float* dp = out + (size_t)2 * P + 3 * (size_t)idx;
                    dp[0] = ox; dp[1] = oy; dp[2] = oz;               // deltas
                    out[(size_t)5 * P + idx] = sqrtf(d2);             // distance
                }
                base += __popc(bal);
            } else {
                cnt += __popc(bal);
            }
        }
        if (!FILL && lane == 0) g_cnt[i] = cnt;
    }
}

// Exclusive scan over 4096 row counts (single block, Hillis-Steele over
// 1024 thread-partials of 4 elements each). Also emits n_pairs.
__global__ void __launch_bounds__(1024) k_scan(float* __restrict__ out, int n_idx) {
    __shared__ int part[1024];
    const int t  = threadIdx.x;
    const int c0 = g_cnt[4 * t + 0];
    const int c1 = g_cnt[4 * t + 1];
    const int c2 = g_cnt[4 * t + 2];
    const int c3 = g_cnt[4 * t + 3];
    const int s  = c0 + c1 + c2 + c3;
    part[t] = s;
    __syncthreads();
    for (int d = 1; d < 1024; d <<= 1) {
        const int v = (t >= d) ? part[t - d] : 0;
        __syncthreads();
        part[t] += v;
        __syncthreads();
    }
    const int excl = part[t] - s;
    g_off[4 * t + 0] = excl;
    g_off[4 * t + 1] = excl + c0;
    g_off[4 * t + 2] = excl + c0 + c1;
    g_off[4 * t + 3] = excl + c0 + c1 + c2;
    if (t == 1023) out[n_idx] = (float)part[1023];   // n_pairs
}

// Padding: pairs region -> -1, deltas/distances -> 0 (out is poisoned 0xAA).
__global__ void k_pad(float* __restrict__ out, int P) {
    const int total = 6 * P;
    for (int idx = blockIdx.x * blockDim.x + threadIdx.x; idx < total;
         idx += gridDim.x * blockDim.x)
        out[idx] = (idx < 2 * P) ? -1.0f : 0.0f;
}

extern "C" void kernel_launch(void* const* d_in, const int* in_sizes, int n_in,
                              void* d_out, int out_size) {
    const float* pos = (const float*)d_in[0];   // [4096, 3] float32
    const float* box = (const float*)d_in[1];   // [3, 3]   float32
    float* out = (float*)d_out;
    const int P = (out_size - 1) / 6;           // MAX_NUM_PAIRS

    k_prep<<<1, 1>>>(box);
    k_pairs<false><<<128, 512>>>(pos, out, P);  // count pass
    k_scan<<<1, 1024>>>(out, 6 * P);            // offsets + n_pairs
    k_pad<<<512, 256>>>(out, P);                // -1 / 0 padding
    k_pairs<true><<<128, 512>>>(pos, out, P);   // ordered fill pass
}

// round 3
// speedup vs baseline: 1.7066x; 1.7066x over previous
#include <cuda_runtime.h>
#include <math.h>

#define NA    4096
#define CUT2  25.0f
#define MAGIC 12582912.0f   // 1.5 * 2^23 : (x+MAGIC)-MAGIC == rint-to-even(x), |x| < 2^22

// Scratch (no device allocation allowed).
__device__ float    g_mat[18];            // [0..8] inv(box), [9..17] box (row-major)
__device__ int      g_diag;               // 1 if box is diagonal (exact-zero off-diag)
__device__ int      g_cnt[NA];            // per-row hit counts
__device__ int      g_off[NA];            // per-row exclusive offsets
__device__ unsigned g_mask[NA * 128];     // per-row hit bitmasks (iteration-granular)

// ---------------------------------------------------------------------------
// 3x3 inverse via cofactors; also detect diagonal box.
// ---------------------------------------------------------------------------
__global__ void k_prep(const float* __restrict__ box) {
    float b[9];
#pragma unroll
    for (int i = 0; i < 9; i++) b[i] = box[i];
    float c00 =  (b[4]*b[8] - b[5]*b[7]);
    float c01 = -(b[3]*b[8] - b[5]*b[6]);
    float c02 =  (b[3]*b[7] - b[4]*b[6]);
    float det = b[0]*c00 + b[1]*c01 + b[2]*c02;

    g_mat[0] = __fdiv_rn(c00, det);
    g_mat[3] = __fdiv_rn(c01, det);
    g_mat[6] = __fdiv_rn(c02, det);
    g_mat[1] = __fdiv_rn(-(b[1]*b[8] - b[2]*b[7]), det);
    g_mat[4] = __fdiv_rn( (b[0]*b[8] - b[2]*b[6]), det);
    g_mat[7] = __fdiv_rn(-(b[0]*b[7] - b[1]*b[6]), det);
    g_mat[2] = __fdiv_rn( (b[1]*b[5] - b[2]*b[4]), det);
    g_mat[5] = __fdiv_rn(-(b[0]*b[5] - b[2]*b[3]), det);
    g_mat[8] = __fdiv_rn( (b[0]*b[4] - b[1]*b[3]), det);
#pragma unroll
    for (int i = 0; i < 9; i++) g_mat[9 + i] = b[i];

    g_diag = (b[1] == 0.0f && b[2] == 0.0f && b[3] == 0.0f &&
              b[5] == 0.0f && b[6] == 0.0f && b[7] == 0.0f) ? 1 : 0;
}

// General minimum-image (explicit _rn ops: no fma contraction, matches R1 numerics).
__device__ __forceinline__ float pair_d2_gen(float dx, float dy, float dz,
                                             const float* m,
                                             float& ox, float& oy, float& oz) {
    float fx = __fadd_rn(__fadd_rn(__fmul_rn(dx, m[0]), __fmul_rn(dy, m[3])), __fmul_rn(dz, m[6]));
    float fy = __fadd_rn(__fadd_rn(__fmul_rn(dx, m[1]), __fmul_rn(dy, m[4])), __fmul_rn(dz, m[7]));
    float fz = __fadd_rn(__fadd_rn(__fmul_rn(dx, m[2]), __fmul_rn(dy, m[5])), __fmul_rn(dz, m[8]));
    float rx = rintf(fx), ry = rintf(fy), rz = rintf(fz);
    float sx = __fadd_rn(__fadd_rn(__fmul_rn(rx, m[9]),  __fmul_rn(ry, m[12])), __fmul_rn(rz, m[15]));
    float sy = __fadd_rn(__fadd_rn(__fmul_rn(rx, m[10]), __fmul_rn(ry, m[13])), __fmul_rn(rz, m[16]));
    float sz = __fadd_rn(__fadd_rn(__fmul_rn(rx, m[11]), __fmul_rn(ry, m[14])), __fmul_rn(rz, m[17]));
    ox = __fsub_rn(dx, sx);
    oy = __fsub_rn(dy, sy);
    oz = __fsub_rn(dz, sz);
    return __fadd_rn(__fadd_rn(__fmul_rn(ox, ox), __fmul_rn(oy, oy)), __fmul_rn(oz, oz));
}

// Diagonal fast path: bit-identical (zero products only affect zero signs).
// Magic-constant round-to-even replaces FRND with two fma-pipe ops.
__device__ __forceinline__ float pair_d2_diag(float dx, float dy, float dz,
                                              float i0, float i1, float i2,
                                              float L0, float L1, float L2,
                                              float& ox, float& oy, float& oz) {
    float rx = __fsub_rn(__fadd_rn(__fmul_rn(dx, i0), MAGIC), MAGIC);
    float ry = __fsub_rn(__fadd_rn(__fmul_rn(dy, i1), MAGIC), MAGIC);
    float rz = __fsub_rn(__fadd_rn(__fmul_rn(dz, i2), MAGIC), MAGIC);
    ox = __fsub_rn(dx, __fmul_rn(rx, L0));
    oy = __fsub_rn(dy, __fmul_rn(ry, L1));
    oz = __fsub_rn(dz, __fmul_rn(rz, L2));
    return __fadd_rn(__fadd_rn(__fmul_rn(ox, ox), __fmul_rn(oy, oy)), __fmul_rn(oz, oz));
}

// ---------------------------------------------------------------------------
// COUNT pass: one warp owns rows {g, NA-1-g}. Stores the hit ballot for every
// 32-candidate iteration into g_mask, and the per-row hit count into g_cnt.
// ---------------------------------------------------------------------------
template <bool DIAG>
__device__ __forceinline__ void count_rows(const float* sxs, const float* sys,
                                           const float* szs, const float* m,
                                           int gw, int lane) {
    const float i0 = m[0], i1 = m[4], i2 = m[8];
    const float L0 = m[9], L1 = m[13], L2 = m[17];
#pragma unroll
    for (int half = 0; half < 2; half++) {
        const int i = half ? (NA - 1 - gw) : gw;
        const float xi = sxs[i], yi = sys[i], zi = szs[i];
        int cnt = 0, it = 0;
        for (int jb = i + 1; jb < NA; jb += 32, it++) {
            const int  j   = jb + lane;
            const bool act = (j < NA);
            const int  jj  = act ? j : 0;
            float ox, oy, oz, d2;
            if (DIAG)
                d2 = pair_d2_diag(xi - sxs[jj], yi - sys[jj], zi - szs[jj],
                                  i0, i1, i2, L0, L1, L2, ox, oy, oz);
            else
                d2 = pair_d2_gen(xi - sxs[jj], yi - sys[jj], zi - szs[jj],
                                 m, ox, oy, oz);
            const bool hit = act && (d2 < CUT2);
            const unsigned bal = __ballot_sync(0xffffffffu, hit);
            if (lane == 0) g_mask[i * 128 + it] = bal;
            cnt += __popc(bal);
        }
        if (lane == 0) g_cnt[i] = cnt;
    }
}

__global__ void __launch_bounds__(256)
k_count(const float* __restrict__ pos) {
    __shared__ float sxs[NA], sys[NA], szs[NA];   // 48 KB
    for (int t = threadIdx.x; t < NA; t += blockDim.x) {
        sxs[t] = pos[3 * t + 0];
        sys[t] = pos[3 * t + 1];
        szs[t] = pos[3 * t + 2];
    }
    __syncthreads();
    float m[18];
#pragma unroll
    for (int k = 0; k < 18; k++) m[k] = g_mat[k];
    const int gw   = (blockIdx.x * blockDim.x + threadIdx.x) >> 5;  // [0, 2048)
    const int lane = threadIdx.x & 31;
    if (g_diag) count_rows<true >(sxs, sys, szs, m, gw, lane);
    else        count_rows<false>(sxs, sys, szs, m, gw, lane);
}

// ---------------------------------------------------------------------------
// FILL pass: reads the bitmasks, warp shfl-prefix over word popcounts gives
// each hit its exact row-major slot; pair math recomputed only for hits.
// ---------------------------------------------------------------------------
template <bool DIAG>
__device__ __forceinline__ void fill_rows(const float* sxs, const float* sys,
                                          const float* szs, const float* m,
                                          float* out, int P, int gw, int lane) {
    const float i0 = m[0], i1 = m[4], i2 = m[8];
    const float L0 = m[9], L1 = m[13], L2 = m[17];
#pragma unroll
    for (int half = 0; half < 2; half++) {
        const int i = half ? (NA - 1 - gw) : gw;
        const float xi = sxs[i], yi = sys[i], zi = szs[i];
        const int n_it = (NA - 1 - i + 31) >> 5;
        int base = g_off[i];
        for (int it0 = 0; it0 < n_it; it0 += 32) {
            const int it = it0 + lane;
            unsigned w = (it < n_it) ? g_mask[i * 128 + it] : 0u;
            const int c = __popc(w);
            int incl = c;                               // warp inclusive scan
#pragma unroll
            for (int d = 1; d < 32; d <<= 1) {
                int v = __shfl_up_sync(0xffffffffu, incl, d);
                if (lane >= d) incl += v;
            }
            int idx = base + incl - c;
            while (w) {
                const int b = __ffs(w) - 1; w &= (w - 1);
                const int j = i + 1 + 32 * it + b;
                float ox, oy, oz, d2;
                if (DIAG)
                    d2 = pair_d2_diag(xi - sxs[j], yi - sys[j], zi - szs[j],
                                      i0, i1, i2, L0, L1, L2, ox, oy, oz);
                else
                    d2 = pair_d2_gen(xi - sxs[j], yi - sys[j], zi - szs[j],
                                     m, ox, oy, oz);
                out[idx]             = (float)i;
                out[(size_t)P + idx] = (float)j;
                float* dp = out + (size_t)2 * P + 3 * (size_t)idx;
                dp[0] = ox; dp[1] = oy; dp[2] = oz;
                out[(size_t)5 * P + idx] = sqrtf(d2);
                idx++;
            }
            base += __shfl_sync(0xffffffffu, incl, 31);  // warp total
        }
    }
}

__global__ void __launch_bounds__(256)
k_fill(const float* __restrict__ pos, float* __restrict__ out, int P) {
    __shared__ float sxs[NA], sys[NA], szs[NA];
    for (int t = threadIdx.x; t < NA; t += blockDim.x) {
        sxs[t] = pos[3 * t + 0];
        sys[t] = pos[3 * t + 1];
        szs[t] = pos[3 * t + 2];
    }
    __syncthreads();
    float m[18];
#pragma unroll
    for (int k = 0; k < 18; k++) m[k] = g_mat[k];
    const int gw   = (blockIdx.x * blockDim.x + threadIdx.x) >> 5;
    const int lane = threadIdx.x & 31;
    if (g_diag) fill_rows<true >(sxs, sys, szs, m, out, P, gw, lane);
    else        fill_rows<false>(sxs, sys, szs, m, out, P, gw, lane);
}

// ---------------------------------------------------------------------------
// Exclusive scan over 4096 row counts (shfl-based, 2 syncthreads) + n_pairs.
// ---------------------------------------------------------------------------
__global__ void __launch_bounds__(1024) k_scan(float* __restrict__ out, int n_idx) {
    __shared__ int wsum[32];
    const int t = threadIdx.x, lane = t & 31, wid = t >> 5;
    const int c0 = g_cnt[4 * t + 0];
    const int c1 = g_cnt[4 * t + 1];
    const int c2 = g_cnt[4 * t + 2];
    const int c3 = g_cnt[4 * t + 3];
    const int s  = c0 + c1 + c2 + c3;
    int incl = s;
#pragma unroll
    for (int d = 1; d < 32; d <<= 1) {
        int v = __shfl_up_sync(0xffffffffu, incl, d);
        if (lane >= d) incl += v;
    }
    if (lane == 31) wsum[wid] = incl;
    __syncthreads();
    if (wid == 0) {
        int wv = wsum[lane];
        int wincl = wv;
#pragma unroll
        for (int d = 1; d < 32; d <<= 1) {
            int v = __shfl_up_sync(0xffffffffu, wincl, d);
            if (lane >= d) wincl += v;
        }
        wsum[lane] = wincl - wv;   // exclusive warp base
        if (lane == 31 ) out[n_idx] = (float)wincl;  // total pairs
    }
    __syncthreads();
    const int excl = (incl - s) + wsum[wid];
    g_off[4 * t + 0] = excl;
    g_off[4 * t + 1] = excl + c0;
    g_off[4 * t + 2] = excl + c0 + c1;
    g_off[4 * t + 3] = excl + c0 + c1 + c2;
}

// Padding via float4: pairs region -> -1, deltas/distances -> 0.
__global__ void __launch_bounds__(256) k_pad(float4* __restrict__ out4, int P) {
    const int total4  = (6 * P) >> 2;
    const int pairs4  = (2 * P) >> 2;
    const float4 neg1 = make_float4(-1.f, -1.f, -1.f, -1.f);
    const float4 zero = make_float4(0.f, 0.f, 0.f, 0.f);
    for (int idx = blockIdx.x * blockDim.x + threadIdx.x; idx < total4;
         idx += gridDim.x * blockDim.x)
        out4[idx] = (idx < pairs4) ? neg1 : zero;
}

extern "C" void kernel_launch(void* const* d_in, const int* in_sizes, int n_in,
                              void* d_out, int out_size) {
    const float* pos = (const float*)d_in[0];   // [4096, 3] float32
    const float* box = (const float*)d_in[1];   // [3, 3]   float32
    float* out = (float*)d_out;
    const int P = (out_size - 1) / 6;           // MAX_NUM_PAIRS

    k_prep<<<1, 1>>>(box);
    k_count<<<256, 256>>>(pos);                 // O(N^2) pass + bitmasks
    k_scan<<<1, 1024>>>(out, 6 * P);            // offsets + n_pairs
    k_pad<<<256, 256>>>((float4*)out, P);       // -1 / 0 padding
    k_fill<<<256, 256>>>(pos, out, P);          // hits-only ordered fill
}

// round 5
// speedup vs baseline: 1.7081x; 1.0009x over previous
#include <cuda_runtime.h>
#include <math.h>

#define NA     4096
#define CUTF   5.0f
#define CUT2   25.0f
#define MAGIC  12582912.0f   // 1.5*2^23 : (x+MAGIC)-MAGIC == rint-to-even(x), |x| < 2^22
#define NCMAX  1024          // max total cells supported

// Scratch (no device allocation allowed).
__device__ float    g_mat[18];        // [0..8] inv(box), [9..17] box (row-major)
__device__ int      g_nc[3];          // cells per dim
__device__ int      g_cs[NCMAX + 1];  // cell start offsets (cell-sorted order)
__device__ float    g_sx[NA], g_sy[NA], g_sz[NA];   // cell-sorted positions
__device__ int      g_sidx[NA];       // cell-sorted -> original index
__device__ int      g_cnt[NA];        // per-row hit counts
__device__ int      g_off[NA];        // per-row exclusive offsets
__device__ unsigned g_mask[NA * 128]; // per-row hit bitmask, ABSOLUTE j indexing

// Identical binning formula must be used everywhere.
__device__ __forceinline__ int cell1d(float x, float L, int nc) {
    int c = (int)((x / L) * (float)nc);
    if (c < 0) c = 0;
    if (c >= nc) c = nc - 1;
    return c;
}

// Diagonal-box minimum image, bit-matching the reference op order (no fma
// contraction; magic-constant round == rint-to-even). Validated R2/R3.
__device__ __forceinline__ float pair_d2_diag(float dx, float dy, float dz,
                                              float i0, float i1, float i2,
                                              float L0, float L1, float L2,
                                              float& ox, float& oy, float& oz) {
    float rx = __fsub_rn(__fadd_rn(__fmul_rn(dx, i0), MAGIC), MAGIC);
    float ry = __fsub_rn(__fadd_rn(__fmul_rn(dy, i1), MAGIC), MAGIC);
    float rz = __fsub_rn(__fadd_rn(__fmul_rn(dz, i2), MAGIC), MAGIC);
    ox = __fsub_rn(dx, __fmul_rn(rx, L0));
    oy = __fsub_rn(dy, __fmul_rn(ry, L1));
    oz = __fsub_rn(dz, __fmul_rn(rz, L2));
    return __fadd_rn(__fadd_rn(__fmul_rn(ox, ox), __fmul_rn(oy, oy)), __fmul_rn(oz, oz));
}

// ---------------------------------------------------------------------------
// Cell build (single block): box inverse (thread 0) + bin + hist + scan +
// scatter into cell-sorted arrays. No grid sync needed.
// ---------------------------------------------------------------------------
__global__ void __launch_bounds__(1024)
k_cells(const float* __restrict__ pos, const float* __restrict__ box) {
    __shared__ int scell[NA];       // 16 KB
    __shared__ int shist[NCMAX];    // 4 KB
    __shared__ int sbase[NCMAX];    // 4 KB
    __shared__ int sfill[NCMAX];    // 4 KB
    __shared__ int wpre[32];
    const int t = threadIdx.x;

    if (t == 0) {   // 3x3 inverse via cofactors (same formula as R2/R3)
        float b[9];
#pragma unroll
        for (int i = 0; i < 9; i++) b[i] = box[i];
        float c00 =  (b[4]*b[8] - b[5]*b[7]);
        float c01 = -(b[3]*b[8] - b[5]*b[6]);
        float c02 =  (b[3]*b[7] - b[4]*b[6]);
        float det = b[0]*c00 + b[1]*c01 + b[2]*c02;
        g_mat[0] = __fdiv_rn(c00, det);
        g_mat[3] = __fdiv_rn(c01, det);
        g_mat[6] = __fdiv_rn(c02, det);
        g_mat[1] = __fdiv_rn(-(b[1]*b[8] - b[2]*b[7]), det);
        g_mat[4] = __fdiv_rn( (b[0]*b[8] - b[2]*b[6]), det);
        g_mat[7] = __fdiv_rn(-(b[0]*b[7] - b[1]*b[6]), det);
        g_mat[2] = __fdiv_rn( (b[1]*b[5] - b[2]*b[4]), det);
        g_mat[5] = __fdiv_rn(-(b[0]*b[5] - b[2]*b[3]), det);
        g_mat[8] = __fdiv_rn( (b[0]*b[4] - b[1]*b[3]), det);
#pragma unroll
        for (int i = 0; i < 9; i++) g_mat[9 + i] = b[i];
    }

    const float L0 = box[0], L1 = box[4], L2 = box[8];
    int ncx = (int)(L0 / CUTF); ncx = max(3, min(ncx, 10));  // width >= cutoff
    int ncy = (int)(L1 / CUTF); ncy = max(3, min(ncy, 10));
    int ncz = (int)(L2 / CUTF); ncz = max(3, min(ncz, 10));
    const int ncells = ncx * ncy * ncz;
    if (t == 0) { g_nc[0] = ncx; g_nc[1] = ncy; g_nc[2] = ncz; }

    shist[t] = 0;                        // blockDim == NCMAX
    __syncthreads();

    for (int a = t; a < NA; a += 1024) {
        const int cx = cell1d(pos[3*a+0], L0, ncx);
        const int cy = cell1d(pos[3*a+1], L1, ncy);
        const int cz = cell1d(pos[3*a+2], L2, ncz);
        const int c  = (cz * ncy + cy) * ncx + cx;
        scell[a] = c;
        atomicAdd(&shist[c], 1);
    }
    __syncthreads();

    // exclusive scan over NCMAX histogram entries (shfl, 2-level)
    const int lane = t & 31, wid = t >> 5;
    const int v = shist[t];
    int incl = v;
#pragma unroll
    for (int d = 1; d < 32; d <<= 1) {
        int u = __shfl_up_sync(0xffffffffu, incl, d);
        if (lane >= d) incl += u;
    }
    if (lane == 31) wpre[wid] = incl;
    __syncthreads();
    if (wid == 0) {
        int wv = wpre[lane], wincl = wv;
#pragma unroll
        for (int d = 1; d < 32; d <<= 1) {
            int u = __shfl_up_sync(0xffffffffu, wincl, d);
            if (lane >= d) wincl += u;
        }
        wpre[lane] = wincl - wv;
    }
    __syncthreads();
    const int excl = incl - v + wpre[wid];
    sbase[t] = excl;
    sfill[t] = 0;
    if (t < ncells) g_cs[t] = excl;
    if (t == 0)     g_cs[ncells] = NA;
    __syncthreads();

    // scatter into cell-sorted arrays (intra-cell order is irrelevant:
    // output order is recovered from the absolute-j bitmask)
    for (int a = t; a < NA; a += 1024) {
        const int c = scell[a];
        const int dst = sbase[c] + atomicAdd(&sfill[c], 1);
        g_sx[dst]   = pos[3*a+0];
        g_sy[dst]   = pos[3*a+1];
        g_sz[dst]   = pos[3*a+2];
        g_sidx[dst] = a;
    }
}

// ---------------------------------------------------------------------------
// COUNT pass: one warp per row i; only 27-cell neighborhood candidates.
// Hits set bit j in an absolute-j per-row bitmask (smem, then global).
// ---------------------------------------------------------------------------
__global__ void __launch_bounds__(256)
k_count(const float* __restrict__ pos) {
    __shared__ unsigned smask[8][128];   // 4 KB
    const int w = threadIdx.x >> 5, lane = threadIdx.x & 31;
    const int i = blockIdx.x * 8 + w;    // 512 blocks x 8 warps = 4096 rows

    const float i0 = g_mat[0], i1 = g_mat[4], i2 = g_mat[8];
    const float L0 = g_mat[9], L1 = g_mat[13], L2 = g_mat[17];
    const int ncx = g_nc[0], ncy = g_nc[1], ncz = g_nc[2];
    const float xi = pos[3*i], yi = pos[3*i+1], zi = pos[3*i+2];

#pragma unroll
    for (int q = 0; q < 4; q++) smask[w][q * 32 + lane] = 0u;
    __syncwarp();

    const int cx = cell1d(xi, L0, ncx);
    const int cy = cell1d(yi, L1, ncy);
    const int cz = cell1d(zi, L2, ncz);

    auto scan_seg = [&](int s, int e) {
        for (int k = s + lane; k < e; k += 32) {
            const int jo = g_sidx[k];
            float ox, oy, oz;
            const float d2 = pair_d2_diag(xi - g_sx[k], yi - g_sy[k], zi - g_sz[k],
                                          i0, i1, i2, L0, L1, L2, ox, oy, oz);
            if (jo > i && d2 < CUT2)
                atomicOr(&smask[w][jo >> 5], 1u << (jo & 31));
        }
    };

    for (int dz = -1; dz <= 1; dz++) {
        int czz = cz + dz; czz += (czz < 0) ? ncz : 0; czz -= (czz >= ncz) ? ncz : 0;
        for (int dy = -1; dy <= 1; dy++) {
            int cyy = cy + dy; cyy += (cyy < 0) ? ncy : 0; cyy -= (cyy >= ncy) ? ncy : 0;
            const int rb = (czz * ncy + cyy) * ncx;
            if (cx > 0 && cx < ncx - 1) {            // 3 x-cells contiguous
                scan_seg(g_cs[rb + cx - 1], g_cs[rb + cx + 2]);
            } else if (cx == 0) {                    // wrap: {0,1} + {ncx-1}
                scan_seg(g_cs[rb],           g_cs[rb + 2]);
                scan_seg(g_cs[rb + ncx - 1], g_cs[rb + ncx]);
            } else {                                 // cx==ncx-1: {ncx-2,ncx-1} + {0}
                scan_seg(g_cs[rb + ncx - 2], g_cs[rb + ncx]);
                scan_seg(g_cs[rb],           g_cs[rb + 1]);
            }
        }
    }
    __syncwarp();

    int c = 0;
#pragma unroll
    for (int q = 0; q < 4; q++) {
        const unsigned mw = smask[w][q * 32 + lane];
        g_mask[i * 128 + q * 32 + lane] = mw;        // coalesced full rewrite
        c += __popc(mw);
    }
    c = __reduce_add_sync(0xffffffffu, c);
    if (lane == 0) g_cnt[i] = c;
}

// ---------------------------------------------------------------------------
// Exclusive scan over 4096 row counts (shfl-based) + n_pairs.
// ---------------------------------------------------------------------------
__global__ void __launch_bounds__(1024) k_scan(float* __restrict__ out, int n_idx) {
    __shared__ int wsum[32];
    const int t = threadIdx.x, lane = t & 31, wid = t >> 5;
    const int c0 = g_cnt[4 * t + 0];
    const int c1 = g_cnt[4 * t + 1];
    const int c2 = g_cnt[4 * t + 2];
    const int c3 = g_cnt[4 * t + 3];
    const int s  = c0 + c1 + c2 + c3;
    int incl = s;
#pragma unroll
    for (int d = 1; d < 32; d <<= 1) {
        int v = __shfl_up_sync(0xffffffffu, incl, d);
        if (lane >= d) incl += v;
    }
    if (lane == 31) wsum[wid] = incl;
    __syncthreads();
    if (wid == 0) {
        int wv = wsum[lane], wincl = wv;
#pragma unroll
        for (int d = 1; d < 32; d <<= 1) {
            int v = __shfl_up_sync(0xffffffffu, wincl, d);
            if (lane >= d) wincl += v;
        }
        wsum[lane] = wincl - wv;
        if (lane == 31) out[n_idx] = (float)wincl;   // n_pairs
    }
    __syncthreads();
    const int excl = (incl - s) + wsum[wid];
    g_off[4 * t + 0] = excl;
    g_off[4 * t + 1] = excl + c0;
    g_off[4 * t + 2] = excl + c0 + c1;
    g_off[4 * t + 3] = excl + c0 + c1 + c2;
}

// ---------------------------------------------------------------------------
// FILL pass: absolute-j bitmask -> exact row-major compaction; recompute math
// only for hits. Padding of the tail is folded in (disjoint index ranges).
// ---------------------------------------------------------------------------
__global__ void __launch_bounds__(256)
k_fill(const float* __restrict__ pos, float* __restrict__ out, int P) {
    __shared__ float sxs[NA], sys[NA], szs[NA];   // 48 KB
    for (int t = threadIdx.x; t < NA; t += blockDim.x) {
        sxs[t] = pos[3 * t + 0];
        sys[t] = pos[3 * t + 1];
        szs[t] = pos[3 * t + 2];
    }
    __syncthreads();

    const float i0 = g_mat[0], i1 = g_mat[4], i2 = g_mat[8];
    const float L0 = g_mat[9], L1 = g_mat[13], L2 = g_mat[17];
    const int gw   = (blockIdx.x * blockDim.x + threadIdx.x) >> 5;  // [0,2048)
    const int lane = threadIdx.x & 31;

#pragma unroll
    for (int half = 0; half < 2; half++) {
        const int i = half ? (NA - 1 - gw) : gw;
        const float xi = sxs[i], yi = sys[i], zi = szs[i];
        int base = g_off[i];
        for (int w0 = 0; w0 < 128; w0 += 32) {
            const int wi = w0 + lane;
            unsigned wv = g_mask[i * 128 + wi];
            const int c = __popc(wv);
            int incl = c;
#pragma unroll
            for (int d = 1; d < 32; d <<= 1) {
                int u = __shfl_up_sync(0xffffffffu, incl, d);
                if (lane >= d) incl += u;
            }
            int idx = base + incl - c;
            while (wv) {
                const int b = __ffs(wv) - 1; wv &= (wv - 1);
                const int j = 32 * wi + b;
                float ox, oy, oz;
                const float d2 = pair_d2_diag(xi - sxs[j], yi - sys[j], zi - szs[j],
                                              i0, i1, i2, L0, L1, L2, ox, oy, oz);
                out[idx]             = (float)i;
                out[(size_t)P + idx] = (float)j;
                float* dp = out + (size_t)2 * P + 3 * (size_t)idx;
                dp[0] = ox; dp[1] = oy; dp[2] = oz;
                out[(size_t)5 * P + idx] = sqrtf(d2);
                idx++;
            }
            base += __shfl_sync(0xffffffffu, incl, 31);
        }
    }

    // tail padding: pairs -> -1, deltas/distances -> 0 (d_out is poisoned)
    const int total  = g_off[NA - 1] + g_cnt[NA - 1];
    const int stride = gridDim.x * blockDim.x;
    for (int idx = total + (int)(blockIdx.x * blockDim.x + threadIdx.x);
         idx < P; idx += stride) {
        out[idx]             = -1.0f;
        out[(size_t)P + idx] = -1.0f;
        float* dp = out + (size_t)2 * P + 3 * (size_t)idx;
        dp[0] = 0.0f; dp[1] = 0.0f; dp[2] = 0.0f;
        out[(size_t)5 * P + idx] = 0.0f;
    }
}

extern "C" void kernel_launch(void* const* d_in, const int* in_sizes, int n_in,
                              void* d_out, int out_size) {
    const float* pos = (const float*)d_in[0];   // [4096, 3] float32
    const float* box = (const float*)d_in[1];   // [3, 3]   float32
    float* out = (float*)d_out;
    const int P = (out_size - 1) / 6;           // MAX_NUM_PAIRS

    k_cells<<<1, 1024>>>(pos, box);             // prep + cell-sort
    k_count<<<512, 256>>>(pos);                 // 27-cell candidates -> bitmasks
    k_scan<<<1, 1024>>>(out, 6 * P);            // offsets + n_pairs
    k_fill<<<256, 256>>>(pos, out, P);          // ordered fill + tail padding
}

// round 6
// speedup vs baseline: 2.0585x; 1.2051x over previous
#include <cuda_runtime.h>
#include <math.h>

#define NA     4096
#define CUTF   5.0f
#define CUT2   25.0f
#define MAGIC  12582912.0f   // 1.5*2^23 : (x+MAGIC)-MAGIC == rint-to-even(x), |x| < 2^22
#define NCMAX  1024
#define CBLK   512           // k_count blocks (8 warps x 512 = 4096 rows)

// Scratch (no device allocation allowed).
__device__ float    g_mat[18];        // [0..8] inv(box), [9..17] box (row-major)
__device__ int      g_nc[3];          // cells per dim
__device__ int      g_cs[NCMAX + 1];  // cell start offsets
__device__ float4   g_spos[NA];       // cell-sorted (x,y,z, idx-bits)
__device__ int      g_cnt[NA];        // per-row hit counts
__device__ int      g_off[NA];        // per-row exclusive offsets
__device__ int      g_total;          // total pairs
__device__ int      g_ticket;        // last-block ticket (reset each call in k_cells)
__device__ unsigned g_mask[NA * 128]; // per-row hit bitmask, ABSOLUTE j indexing

__device__ __forceinline__ int cell1d(float x, float L, int nc) {
    int c = (int)((x / L) * (float)nc);
    if (c < 0) c = 0;
    if (c >= nc) c = nc - 1;
    return c;
}

// Diagonal-box minimum image, bit-matching reference op order (validated R2-R4).
__device__ __forceinline__ float pair_d2_diag(float dx, float dy, float dz,
                                              float i0, float i1, float i2,
                                              float L0, float L1, float L2,
                                              float& ox, float& oy, float& oz) {
    float rx = __fsub_rn(__fadd_rn(__fmul_rn(dx, i0), MAGIC), MAGIC);
    float ry = __fsub_rn(__fadd_rn(__fmul_rn(dy, i1), MAGIC), MAGIC);
    float rz = __fsub_rn(__fadd_rn(__fmul_rn(dz, i2), MAGIC), MAGIC);
    ox = __fsub_rn(dx, __fmul_rn(rx, L0));
    oy = __fsub_rn(dy, __fmul_rn(ry, L1));
    oz = __fsub_rn(dz, __fmul_rn(rz, L2));
    return __fadd_rn(__fadd_rn(__fmul_rn(ox, ox), __fmul_rn(oy, oy)), __fmul_rn(oz, oz));
}

// ---------------------------------------------------------------------------
// Cell build (single block): inverse + ticket reset + bin + hist + scan +
// scatter into cell-sorted float4 array.
// ---------------------------------------------------------------------------
__global__ void __launch_bounds__(1024)
k_cells(const float* __restrict__ pos, const float* __restrict__ box) {
    __shared__ int scell[NA];
    __shared__ int shist[NCMAX];
    __shared__ int sbase[NCMAX];
    __shared__ int sfill[NCMAX];
    __shared__ int wpre[32];
    const int t = threadIdx.x;

    if (t == 0) {
        float b[9];
#pragma unroll
        for (int i = 0; i < 9; i++) b[i] = box[i];
        float c00 =  (b[4]*b[8] - b[5]*b[7]);
        float c01 = -(b[3]*b[8] - b[5]*b[6]);
        float c02 =  (b[3]*b[7] - b[4]*b[6]);
        float det = b[0]*c00 + b[1]*c01 + b[2]*c02;
        g_mat[0] = __fdiv_rn(c00, det);
        g_mat[3] = __fdiv_rn(c01, det);
        g_mat[6] = __fdiv_rn(c02, det);
        g_mat[1] = __fdiv_rn(-(b[1]*b[8] - b[2]*b[7]), det);
        g_mat[4] = __fdiv_rn( (b[0]*b[8] - b[2]*b[6]), det);
        g_mat[7] = __fdiv_rn(-(b[0]*b[7] - b[1]*b[6]), det);
        g_mat[2] = __fdiv_rn( (b[1]*b[5] - b[2]*b[4]), det);
        g_mat[5] = __fdiv_rn(-(b[0]*b[5] - b[2]*b[3]), det);
        g_mat[8] = __fdiv_rn( (b[0]*b[4] - b[1]*b[3]), det);
#pragma unroll
        for (int i = 0; i < 9; i++) g_mat[9 + i] = b[i];
        g_ticket = 0;
    }

    const float L0 = box[0], L1 = box[4], L2 = box[8];
    int ncx = (int)(L0 / CUTF); ncx = max(3, min(ncx, 10));
    int ncy = (int)(L1 / CUTF); ncy = max(3, min(ncy, 10));
    int ncz = (int)(L2 / CUTF); ncz = max(3, min(ncz, 10));
    const int ncells = ncx * ncy * ncz;
    if (t == 0) { g_nc[0] = ncx; g_nc[1] = ncy; g_nc[2] = ncz; }

    shist[t] = 0;
    __syncthreads();

    for (int a = t; a < NA; a += 1024) {
        const int cx = cell1d(pos[3*a+0], L0, ncx);
        const int cy = cell1d(pos[3*a+1], L1, ncy);
        const int cz = cell1d(pos[3*a+2], L2, ncz);
        const int c  = (cz * ncy + cy) * ncx + cx;
        scell[a] = c;
        atomicAdd(&shist[c], 1);
    }
    __syncthreads();

    const int lane = t & 31, wid = t >> 5;
    const int v = shist[t];
    int incl = v;
#pragma unroll
    for (int d = 1; d < 32; d <<= 1) {
        int u = __shfl_up_sync(0xffffffffu, incl, d);
        if (lane >= d) incl += u;
    }
    if (lane == 31) wpre[wid] = incl;
    __syncthreads();
    if (wid == 0) {
        int wv = wpre[lane], wincl = wv;
#pragma unroll
        for (int d = 1; d < 32; d <<= 1) {
            int u = __shfl_up_sync(0xffffffffu, wincl, d);
            if (lane >= d) wincl += u;
        }
        wpre[lane] = wincl - wv;
    }
    __syncthreads();
    const int excl = incl - v + wpre[wid];
    sbase[t] = excl;
    sfill[t] = 0;
    if (t < ncells) g_cs[t] = excl;
    if (t == 0)     g_cs[ncells] = NA;
    __syncthreads();

    for (int a = t; a < NA; a += 1024) {
        const int c = scell[a];
        const int dst = sbase[c] + atomicAdd(&sfill[c], 1);
        g_spos[dst] = make_float4(pos[3*a+0], pos[3*a+1], pos[3*a+2],
                                  __int_as_float(a));
    }
}

// ---------------------------------------------------------------------------
// COUNT pass (warp per row, float4 candidates) + fused terminal scan
// (last block computes g_off / g_total / out[n_idx]).
// ---------------------------------------------------------------------------
__global__ void __launch_bounds__(256)
k_count(const float* __restrict__ pos, float* __restrict__ out, int n_idx) {
    __shared__ unsigned smask[8][128];
    __shared__ int s_last;
    const int w = threadIdx.x >> 5, lane = threadIdx.x & 31;
    const int i = blockIdx.x * 8 + w;

    const float i0 = g_mat[0], i1 = g_mat[4], i2 = g_mat[8];
    const float L0 = g_mat[9], L1 = g_mat[13], L2 = g_mat[17];
    const int ncx = g_nc[0], ncy = g_nc[1], ncz = g_nc[2];
    const float xi = pos[3*i], yi = pos[3*i+1], zi = pos[3*i+2];

#pragma unroll
    for (int q = 0; q < 4; q++) smask[w][q * 32 + lane] = 0u;
    __syncwarp();

    const int cx = cell1d(xi, L0, ncx);
    const int cy = cell1d(yi, L1, ncy);
    const int cz = cell1d(zi, L2, ncz);

    auto scan_seg = [&](int s, int e) {
        for (int k = s + lane; k < e; k += 32) {
            const float4 p = g_spos[k];
            const int jo = __float_as_int(p.w);
            float ox, oy, oz;
            const float d2 = pair_d2_diag(xi - p.x, yi - p.y, zi - p.z,
                                          i0, i1, i2, L0, L1, L2, ox, oy, oz);
            if (jo > i && d2 < CUT2)
                atomicOr(&smask[w][jo >> 5], 1u << (jo & 31));
        }
    };

    for (int dz = -1; dz <= 1; dz++) {
        int czz = cz + dz; czz += (czz < 0) ? ncz : 0; czz -= (czz >= ncz) ? ncz : 0;
        for (int dy = -1; dy <= 1; dy++) {
            int cyy = cy + dy; cyy += (cyy < 0) ? ncy : 0; cyy -= (cyy >= ncy) ? ncy : 0;
            const int rb = (czz * ncy + cyy) * ncx;
            if (cx > 0 && cx < ncx - 1) {
                scan_seg(g_cs[rb + cx - 1], g_cs[rb + cx + 2]);
            } else if (cx == 0) {
                scan_seg(g_cs[rb],           g_cs[rb + 2]);
                scan_seg(g_cs[rb + ncx - 1], g_cs[rb + ncx]);
            } else {
                scan_seg(g_cs[rb + ncx - 2], g_cs[rb + ncx]);
                scan_seg(g_cs[rb],           g_cs[rb + 1]);
            }
        }
    }
    __syncwarp();

    // write mask row as uint4 (coalesced), count bits
    uint4 mv = make_uint4(smask[w][4*lane], smask[w][4*lane+1],
                          smask[w][4*lane+2], smask[w][4*lane+3]);
    ((uint4*)(g_mask + (size_t)i * 128))[lane] = mv;
    int c = __popc(mv.x) + __popc(mv.y) + __popc(mv.z) + __popc(mv.w);
    c = __reduce_add_sync(0xffffffffu, c);
    if (lane == 0) g_cnt[i] = c;

    // -------- fused terminal scan: last block to finish does it ----------
    __syncthreads();
    __threadfence();
    if (threadIdx.x == 0)
        s_last = (atomicAdd(&g_ticket, 1) == CBLK - 1);
    __syncthreads();
    if (!s_last) return;
    __threadfence();

    // 256 threads scan 4096 counts: 16 per thread
    __shared__ int wsum[8];
    const int t = threadIdx.x;
    int cv[16], s = 0;
#pragma unroll
    for (int k = 0; k < 16; k++) { cv[k] = g_cnt[16 * t + k]; s += cv[k]; }
    int incl = s;
#pragma unroll
    for (int d = 1; d < 32; d <<= 1) {
        int u = __shfl_up_sync(0xffffffffu, incl, d);
        if (lane >= d) incl += u;
    }
    if (lane == 31) wsum[w] = incl;
    __syncthreads();
    int wbase = 0;
#pragma unroll
    for (int q = 0; q < 8; q++) wbase += (q < w) ? wsum[q] : 0;
    int run = wbase + incl - s;
#pragma unroll
    for (int k = 0; k < 16; k++) { g_off[16 * t + k] = run; run += cv[k]; }
    if (t == 255) { g_total = run; out[n_idx] = (float)run; }
}

// ---------------------------------------------------------------------------
// FILL pass: warp per row, uint4 mask load, ONE warp scan, serial emit
// (~0.5 hits/lane). Contiguous tail padding folded in.
// ---------------------------------------------------------------------------
__global__ void __launch_bounds__(256)
k_fill(const float* __restrict__ pos, float* __restrict__ out, int P) {
    const int w = threadIdx.x >> 5, lane = threadIdx.x & 31;
    const int i = blockIdx.x * 8 + w;             // 512 blocks x 8 warps

    const float i0 = g_mat[0], i1 = g_mat[4], i2 = g_mat[8];
    const float L0 = g_mat[9], L1 = g_mat[13], L2 = g_mat[17];
    const float xi = pos[3*i], yi = pos[3*i+1], zi = pos[3*i+2];

    const uint4 mv = ((const uint4*)(g_mask + (size_t)i * 128))[lane];
    const int c = __popc(mv.x) + __popc(mv.y) + __popc(mv.z) + __popc(mv.w);
    int incl = c;
#pragma unroll
    for (int d = 1; d < 32; d <<= 1) {
        int u = __shfl_up_sync(0xffffffffu, incl, d);
        if (lane >= d) incl += u;
    }
    int idx = g_off[i] + incl - c;

    unsigned ws[4] = {mv.x, mv.y, mv.z, mv.w};
#pragma unroll
    for (int q = 0; q < 4; q++) {
        unsigned wv = ws[q];
        while (wv) {
            const int b = __ffs(wv) - 1; wv &= (wv - 1);
            const int j = 128 * lane + 32 * q + b;
            float ox, oy, oz;
            const float d2 = pair_d2_diag(xi - __ldg(pos + 3*j),
                                          yi - __ldg(pos + 3*j + 1),
                                          zi - __ldg(pos + 3*j + 2),
                                          i0, i1, i2, L0, L1, L2, ox, oy, oz);
            out[idx]             = (float)i;
            out[(size_t)P + idx] = (float)j;
            float* dp = out + (size_t)2 * P + 3 * (size_t)idx;
            dp[0] = ox; dp[1] = oy; dp[2] = oz;
            out[(size_t)5 * P + idx] = sqrtf(d2);
            idx++;
        }
    }

    // ---- contiguous tail padding: 4 regions ----
    const int total = g_total;
    const int tid   = blockIdx.x * blockDim.x + threadIdx.x;
    const int nthr  = gridDim.x * blockDim.x;
    const int tail  = P - total;
    for (int k = tid; k < tail; k += nthr) {                 // pair_i / pair_j
        out[total + k]             = -1.0f;
        out[(size_t)P + total + k] = -1.0f;
    }
    const int dtail = 3 * tail;                              // deltas tail
    float* dbase = out + (size_t)2 * P + 3 * (size_t)total;
    for (int k = tid; k < dtail; k += nthr) dbase[k] = 0.0f;
    for (int k = tid; k < tail; k += nthr)                   // distances tail
        out[(size_t)5 * P + total + k] = 0.0f;
}

extern "C" void kernel_launch(void* const* d_in, const int* in_sizes, int n_in,
                              void* d_out, int out_size) {
    const float* pos = (const float*)d_in[0];   // [4096, 3] float32
    const float* box = (const float*)d_in[1];   // [3, 3]   float32
    float* out = (float*)d_out;
    const int P = (out_size - 1) / 6;           // MAX_NUM_PAIRS

    k_cells<<<1, 1024>>>(pos, box);             // prep + cell-sort + ticket reset
    k_count<<<CBLK, 256>>>(pos, out, 6 * P);    // bitmasks + fused scan/n_pairs
    k_fill<<<512, 256>>>(pos, out, P);          // ordered fill + tail padding
}